// round 17
// baseline (speedup 1.0000x reference)
#include <cuda_runtime.h>
#include <cuda_bf16.h>
#include <cuda_fp16.h>
#include <math.h>

#define NN 100000
#define EE 1600000
#define INF_ 128
#define DD 32
#define HH 4
#define DEG 16
#define ALPHA 0.2f

typedef unsigned int u32;

// Scratch (static __device__ — no allocations allowed)
__device__ __half g_X1h[NN * 128];   // lrelu(X@W1.T) in fp16, node-major [n][h*32+d]
__device__ float  g_s0[NN * HH];
__device__ float  g_s1[NN * HH];
__device__ u32    g_maxu[HH];
__device__ u32    g_minu[HH];

__device__ __forceinline__ u32 flipf(float f) {
    u32 u = __float_as_uint(f);
    return (u >> 31) ? ~u : (u | 0x80000000u);
}
__device__ __forceinline__ float unflipf(u32 e) {
    return (e >> 31) ? __uint_as_float(e & 0x7fffffffu) : __uint_as_float(~e);
}

// pack a pair of floats into packed fp16x2
__device__ __forceinline__ u32 packf16(float a, float b) {
    __half2 h = __floats2half2_rn(a, b);
    return *(u32*)&h;
}

__device__ __forceinline__ void mma_f16(float (&d)[4], const u32 (&a)[4], const u32 (&b)[2]) {
    asm volatile(
        "mma.sync.aligned.m16n8k16.row.col.f32.f16.f16.f32 "
        "{%0,%1,%2,%3}, {%4,%5,%6,%7}, {%8,%9}, {%0,%1,%2,%3};\n"
        : "+f"(d[0]), "+f"(d[1]), "+f"(d[2]), "+f"(d[3])
        : "r"(a[0]), "r"(a[1]), "r"(a[2]), "r"(a[3]), "r"(b[0]), "r"(b[1]));
}

// Fragment-layout smem indexing: A frag 4 u32/lane, B frag 2 u32/lane
__device__ __forceinline__ int afrag_idx(int rr, int kp) {
    int mt = rr >> 4, rloc = rr & 15, g = rloc & 7, hi8 = rloc >> 3;
    int kt = kp >> 3, kp7 = kp & 7, tq = kp7 & 3, khalf = kp7 >> 2;
    return (((mt * 2 + kt) * 32) + (g * 4 + tq)) * 4 + (hi8 + 2 * khalf);
}
__device__ __forceinline__ int bfrag_idx(int cc, int kp) {
    int nt = cc >> 3, g = cc & 7;
    int kt = kp >> 3, kp7 = kp & 7, tq = kp7 & 3, khalf = kp7 >> 2;
    return (((nt * 2 + kt) * 32) + (g * 4 + tq)) * 2 + khalf;
}

// ---------------------------------------------------------------------------
// K1: FUSED. C[:, 0:256] = leakyrelu(X @ [W0;W1].T), single-pass fp16 mma.
// One CTA = 512 threads (16 warps), BM=64 x BN=256 x BK=32.
// warpM = wid>>3 (2), warpNN = wid&7 (8): region = warpNN>>2 (0:W0->s0,
// 1:W1->s1+X1), head = warpNN&3. X loaded ONCE (vs twice with grid.y=2).
// Register double-buffered LDGs; inner loop = LDS.128/64 + HMMA only.
// ---------------------------------------------------------------------------
__global__ void __launch_bounds__(512)
gemm_scores_tc_kernel(const float* __restrict__ X,
                      const float* __restrict__ W0,
                      const float* __restrict__ W1,
                      const float* __restrict__ a0)
{
    __shared__ u32 Afr[4 * 2 * 32 * 4];    // 1024 u32 (fp16x2 fragments)
    __shared__ u32 Bfr[32 * 2 * 32 * 2];   // 4096 u32 (256 cols)

    const int tid    = threadIdx.x;
    const int lane   = tid & 31;
    const int wid    = tid >> 5;
    const int warpM  = wid >> 3;     // 0..1
    const int warpNN = wid & 7;      // 0..7
    const int region = warpNN >> 2;  // 0: W0, 1: W1
    const int h      = warpNN & 3;   // head
    const int g      = lane >> 2;
    const int tq     = lane & 3;

    const int mbase = blockIdx.x * 64;

    // Per-thread load coords
    const int ar = tid >> 3;               // 0..63 (A row)
    const int as = tid & 7;                // A k-float4 slot
    const int arow = mbase + ar;
    const int bn = tid >> 3;               // 0..63 base B col; +64 per i
    const int bs = tid & 7;

    float acc[2][4][4];
#pragma unroll
    for (int m = 0; m < 2; m++)
#pragma unroll
        for (int n = 0; n < 4; n++)
#pragma unroll
            for (int j = 0; j < 4; j++) acc[m][n][j] = 0.0f;

    // ---- prologue: load kc=0 into registers ----
    float4 pa, pb[4];
    pa = (arow < NN) ? *(const float4*)(X + arow * 128 + as * 4)
                     : make_float4(0.f, 0.f, 0.f, 0.f);
#pragma unroll
    for (int i = 0; i < 4; i++) {
        int n = bn + 64 * i;               // 0..255
        const float* Wp = (n < 128) ? (W0 + n * 128) : (W1 + (n - 128) * 128);
        pb[i] = *(const float4*)(Wp + bs * 4);
    }

    for (int kc = 0; kc < 128; kc += 32) {
        // ---- pack + store the prefetched tile ----
        {
            int i0 = afrag_idx(ar, 2 * as);
            int i1 = afrag_idx(ar, 2 * as + 1);
            Afr[i0] = packf16(pa.x, pa.y);
            Afr[i1] = packf16(pa.z, pa.w);
        }
#pragma unroll
        for (int i = 0; i < 4; i++) {
            int n = bn + 64 * i;
            int i0 = bfrag_idx(n, 2 * bs);
            int i1 = bfrag_idx(n, 2 * bs + 1);
            Bfr[i0] = packf16(pb[i].x, pb[i].y);
            Bfr[i1] = packf16(pb[i].z, pb[i].w);
        }
        __syncthreads();

        // ---- prefetch next kc while computing this one ----
        const int kn = kc + 32;
        if (kn < 128) {
            pa = (arow < NN) ? *(const float4*)(X + arow * 128 + kn + as * 4)
                             : make_float4(0.f, 0.f, 0.f, 0.f);
#pragma unroll
            for (int i = 0; i < 4; i++) {
                int n = bn + 64 * i;
                const float* Wp = (n < 128) ? (W0 + n * 128) : (W1 + (n - 128) * 128);
                pb[i] = *(const float4*)(Wp + kn + bs * 4);
            }
        }

#pragma unroll
        for (int kt = 0; kt < 2; kt++) {
            u32 afr[2][4];
#pragma unroll
            for (int m = 0; m < 2; m++) {
                const int abase = (((warpM * 2 + m) * 2 + kt) * 32 + lane) * 4;
                uint4 vh = *(const uint4*)(&Afr[abase]);
                afr[m][0] = vh.x; afr[m][1] = vh.y; afr[m][2] = vh.z; afr[m][3] = vh.w;
            }
            u32 bfr[4][2];
#pragma unroll
            for (int n = 0; n < 4; n++) {
                const int bbase = (((warpNN * 4 + n) * 2 + kt) * 32 + lane) * 2;
                uint2 vh = *(const uint2*)(&Bfr[bbase]);
                bfr[n][0] = vh.x; bfr[n][1] = vh.y;
            }
#pragma unroll
            for (int m = 0; m < 2; m++)
#pragma unroll
                for (int n = 0; n < 4; n++)
                    mma_f16(acc[m][n], afr[m], bfr[n]);
        }
        __syncthreads();
    }

    float av0[4], av1[4];
#pragma unroll
    for (int n = 0; n < 4; n++) {
        int dcol = n * 8 + 2 * tq;     // d within head, 0..31
        av0[n] = a0[h * 32 + dcol];
        av1[n] = a0[h * 32 + dcol + 1];
    }

    float* sdst = (region == 0) ? g_s0 : g_s1;
    const bool storeX1 = (region == 1);

#pragma unroll
    for (int m = 0; m < 2; m++) {
        const int r0 = mbase + warpM * 32 + m * 16 + g;
        const int r1 = r0 + 8;
        float p0 = 0.f, p1 = 0.f;
        float cr[4][4];
#pragma unroll
        for (int n = 0; n < 4; n++) {
#pragma unroll
            for (int j = 0; j < 4; j++) {
                float v = acc[m][n][j];
                cr[n][j] = v > 0.f ? v : ALPHA * v;
            }
            p0 = fmaf(cr[n][0], av0[n], p0);
            p0 = fmaf(cr[n][1], av1[n], p0);
            p1 = fmaf(cr[n][2], av0[n], p1);
            p1 = fmaf(cr[n][3], av1[n], p1);
        }
        p0 += __shfl_xor_sync(0xffffffffu, p0, 1);
        p0 += __shfl_xor_sync(0xffffffffu, p0, 2);
        p1 += __shfl_xor_sync(0xffffffffu, p1, 1);
        p1 += __shfl_xor_sync(0xffffffffu, p1, 2);

        if (tq == 0) {
            if (r0 < NN) sdst[r0 * 4 + h] = p0;
            if (r1 < NN) sdst[r1 * 4 + h] = p1;
        }
        if (storeX1) {
#pragma unroll
            for (int n = 0; n < 4; n++) {
                const int x1c = h * 32 + n * 8 + 2 * tq;
                if (r0 < NN)
                    *(__half2*)(&g_X1h[r0 * 128 + x1c]) = __floats2half2_rn(cr[n][0], cr[n][1]);
                if (r1 < NN)
                    *(__half2*)(&g_X1h[r1 * 128 + x1c]) = __floats2half2_rn(cr[n][2], cr[n][3]);
            }
        }
    }
}

// ---------------------------------------------------------------------------
// K2a: init min/max encodings
// ---------------------------------------------------------------------------
__global__ void init_minmax_kernel()
{
    int t = threadIdx.x;
    if (t < HH) { g_maxu[t] = 0u; g_minu[t] = 0xffffffffu; }
}

// ---------------------------------------------------------------------------
// K2b: per-head global min/max of att[h,e] = s0[e/16][h] + s1[col[e]][h]
// ---------------------------------------------------------------------------
__global__ void __launch_bounds__(256)
minmax_kernel(const int* __restrict__ colIdx)
{
    u32 umax[HH], umin[HH];
#pragma unroll
    for (int h = 0; h < HH; h++) { umax[h] = 0u; umin[h] = 0xffffffffu; }

    const int4* c4p = (const int4*)colIdx;
    const int nq = EE / 4;
    const int stride = gridDim.x * blockDim.x;
    for (int i = blockIdx.x * blockDim.x + threadIdx.x; i < nq; i += stride) {
        const int src = i >> 2;
        const int4 c4 = c4p[i];
        const float4 s0v = *(const float4*)(&g_s0[src * 4]);
        const int cs[4] = {c4.x, c4.y, c4.z, c4.w};
#pragma unroll
        for (int j = 0; j < 4; j++) {
            const float4 s1v = *(const float4*)(&g_s1[cs[j] * 4]);
            u32 u0 = flipf(s0v.x + s1v.x);
            u32 u1 = flipf(s0v.y + s1v.y);
            u32 u2 = flipf(s0v.z + s1v.z);
            u32 u3 = flipf(s0v.w + s1v.w);
            umax[0] = max(umax[0], u0); umin[0] = min(umin[0], u0);
            umax[1] = max(umax[1], u1); umin[1] = min(umin[1], u1);
            umax[2] = max(umax[2], u2); umin[2] = min(umin[2], u2);
            umax[3] = max(umax[3], u3); umin[3] = min(umin[3], u3);
        }
    }

#pragma unroll
    for (int off = 16; off > 0; off >>= 1) {
#pragma unroll
        for (int h = 0; h < HH; h++) {
            umax[h] = max(umax[h], __shfl_xor_sync(0xffffffffu, umax[h], off));
            umin[h] = min(umin[h], __shfl_xor_sync(0xffffffffu, umin[h], off));
        }
    }

    __shared__ u32 sred[8][8];
    int warp = threadIdx.x >> 5;
    int lane = threadIdx.x & 31;
    if (lane == 0) {
#pragma unroll
        for (int h = 0; h < HH; h++) {
            sred[warp][h]     = umax[h];
            sred[warp][4 + h] = umin[h];
        }
    }
    __syncthreads();
    if (threadIdx.x < 4) {
        u32 v = 0u;
        for (int w2 = 0; w2 < 8; w2++) v = max(v, sred[w2][threadIdx.x]);
        atomicMax(&g_maxu[threadIdx.x], v);
    } else if (threadIdx.x < 8) {
        u32 v = 0xffffffffu;
        for (int w2 = 0; w2 < 8; w2++) v = min(v, sred[w2][threadIdx.x]);
        atomicMin(&g_minu[threadIdx.x - 4], v);
    }
}

// ---------------------------------------------------------------------------
// K3: one warp per node, all 4 heads; weights staged via smem (no shuffles)
// ---------------------------------------------------------------------------
__global__ void __launch_bounds__(256)
aggregate_kernel(const int* __restrict__ colIdx, float* __restrict__ out)
{
    __shared__ float wS[8][4][20];
    __shared__ int   cS[8][16];

    const int n = (blockIdx.x * blockDim.x + threadIdx.x) >> 5;
    if (n >= NN) return;
    const int warp = (threadIdx.x >> 5) & 7;
    const int lane = threadIdx.x & 31;
    const int h    = lane >> 3;
    const int e16  = lane & 15;
    const int hh   = lane >> 4;

    const int c = colIdx[n * DEG + e16];
    const float mxa = unflipf(g_maxu[hh]);
    const float mna = unflipf(g_minu[hh]);
    const float mxb = unflipf(g_maxu[hh + 2]);
    const float mnb = unflipf(g_minu[hh + 2]);
    const float inva = __fdividef(1.0f, mxa - mna);
    const float invb = __fdividef(1.0f, mxb - mnb);
    const float s0a = g_s0[n * 4 + hh];
    const float s0b = g_s0[n * 4 + hh + 2];
    const float s1a = g_s1[c * 4 + hh];
    const float s1b = g_s1[c * 4 + hh + 2];
    const float w01 = __expf((s0a + s1a - mna) * inva);
    const float w23 = __expf((s0b + s1b - mnb) * invb);

    wS[warp][hh][e16]     = w01;
    wS[warp][hh + 2][e16] = w23;
    if (lane < 16) cS[warp][e16] = c;
    __syncwarp(0xffffffffu);

    float4 wv[4];
    int4   cv[4];
#pragma unroll
    for (int i = 0; i < 4; i++) {
        wv[i] = *(const float4*)(&wS[warp][h][4 * i]);
        cv[i] = *(const int4*)(&cS[warp][4 * i]);
    }
    float4 t0 = make_float4(wv[0].x + wv[1].x, wv[0].y + wv[1].y,
                            wv[0].z + wv[1].z, wv[0].w + wv[1].w);
    float4 t1 = make_float4(wv[2].x + wv[3].x, wv[2].y + wv[3].y,
                            wv[2].z + wv[3].z, wv[2].w + wv[3].w);
    const float wsum = (t0.x + t1.x) + (t0.y + t1.y) + (t0.z + t1.z) + (t0.w + t1.w);
    const float invSum = __fdividef(1.0f, wsum);

    float4 acc = make_float4(0.f, 0.f, 0.f, 0.f);
    const __half* basep = g_X1h + lane * 4;

#define AGG_EDGE(CE, WE)                                        \
    {                                                           \
        const uint2 u = *(const uint2*)(basep + (CE) * 128);    \
        const float2 f0 = __half22float2(*(const __half2*)&u.x);\
        const float2 f1 = __half22float2(*(const __half2*)&u.y);\
        acc.x = fmaf((WE), f0.x, acc.x);                        \
        acc.y = fmaf((WE), f0.y, acc.y);                        \
        acc.z = fmaf((WE), f1.x, acc.z);                        \
        acc.w = fmaf((WE), f1.y, acc.w);                        \
    }

#pragma unroll
    for (int i = 0; i < 4; i++) {
        AGG_EDGE(cv[i].x, wv[i].x);
        AGG_EDGE(cv[i].y, wv[i].y);
        AGG_EDGE(cv[i].z, wv[i].z);
        AGG_EDGE(cv[i].w, wv[i].w);
    }
#undef AGG_EDGE

    float4 r = make_float4(acc.x * invSum, acc.y * invSum, acc.z * invSum, acc.w * invSum);
    *(float4*)(&out[n * 128 + lane * 4]) = r;
}

// ---------------------------------------------------------------------------
extern "C" void kernel_launch(void* const* d_in, const int* in_sizes, int n_in,
                              void* d_out, int out_size)
{
    const float* X    = (const float*)d_in[0];
    const float* W0   = (const float*)d_in[1];
    const float* W1   = (const float*)d_in[2];
    const float* a0   = (const float*)d_in[3];
    // d_in[4] = edge_src (structured: e/16), unused
    const int* colIdx = (const int*)d_in[5];
    float* out = (float*)d_out;

    init_minmax_kernel<<<1, 32>>>();
    gemm_scores_tc_kernel<<<(NN + 63) / 64, 512>>>(X, W0, W1, a0);
    minmax_kernel<<<296, 256>>>(colIdx);
    aggregate_kernel<<<(NN * 32 + 255) / 256, 256>>>(colIdx, out);
}